// round 10
// baseline (speedup 1.0000x reference)
#include <cuda_runtime.h>
#include <cuda_fp16.h>
#include <math.h>
#include <stdint.h>

#define T_TOK   8192
#define D_IN    1024
#define HID     2048
#define D_OUT   1024
#define NEXP    8
#define MAXROWS 17408
#define NTILES  (MAXROWS/128)   // 136
#define WSCALE     32.0f
#define WSCALE_INV 0.03125f

// ---------------- scratch (16B-access targets are 256B aligned) ----------------
__device__ int   g_topi[T_TOK * 2];
__device__ float g_topv[T_TOK * 2];
__device__ int   g_row_token[MAXROWS];
__device__ float g_row_weight[MAXROWS];
__device__ int   g_slot[T_TOK * 2];
__device__ int   g_tile_expert[NTILES];
__device__ __align__(256) float g_eo[(size_t)MAXROWS * D_OUT];
__device__ __align__(256) __half g_x  [(size_t)T_TOK   * D_IN];
__device__ __align__(256) __half g_h  [(size_t)MAXROWS * HID];
__device__ __align__(256) __half g_hs [(size_t)T_TOK   * HID];
__device__ __align__(256) __half g_w1t_hi[(size_t)NEXP * HID * D_IN];
__device__ __align__(256) __half g_w1t_lo[(size_t)NEXP * HID * D_IN];
__device__ __align__(256) __half g_w2t_hi[(size_t)NEXP * D_OUT * HID];
__device__ __align__(256) __half g_w2t_lo[(size_t)NEXP * D_OUT * HID];
__device__ __align__(256) __half g_s1t_hi[(size_t)HID * D_IN];
__device__ __align__(256) __half g_s1t_lo[(size_t)HID * D_IN];
__device__ __align__(256) __half g_s2t_hi[(size_t)D_OUT * HID];
__device__ __align__(256) __half g_s2t_lo[(size_t)D_OUT * HID];

// ---------------- helpers (base-ISA: cp.async, ldmatrix, mma.sync) ----------
__device__ __forceinline__ uint32_t smem_u32(const void* p) {
    uint32_t a;
    asm("{ .reg .u64 t; cvta.to.shared.u64 t, %1; cvt.u32.u64 %0, t; }" : "=r"(a) : "l"(p));
    return a;
}
__device__ __forceinline__ void cp16(uint32_t s, const void* g, int srcsz) {
    asm volatile("cp.async.cg.shared.global [%0], [%1], 16, %2;" :: "r"(s), "l"(g), "r"(srcsz));
}
__device__ __forceinline__ void cp_commit() { asm volatile("cp.async.commit_group;" ::: "memory"); }
__device__ __forceinline__ void cp_wait1()  { asm volatile("cp.async.wait_group 1;" ::: "memory"); }
__device__ __forceinline__ void cp_wait0()  { asm volatile("cp.async.wait_group 0;" ::: "memory"); }
__device__ __forceinline__ void ldm_x4(uint32_t* r, uint32_t addr) {
    asm volatile("ldmatrix.sync.aligned.m8n8.x4.shared.b16 {%0,%1,%2,%3}, [%4];"
                 : "=r"(r[0]), "=r"(r[1]), "=r"(r[2]), "=r"(r[3]) : "r"(addr));
}
__device__ __forceinline__ void mma_f16(float* d, const uint32_t* a, const uint32_t* b) {
    asm volatile(
        "mma.sync.aligned.m16n8k16.row.col.f32.f16.f16.f32 "
        "{%0,%1,%2,%3}, {%4,%5,%6,%7}, {%8,%9}, {%0,%1,%2,%3};"
        : "+f"(d[0]), "+f"(d[1]), "+f"(d[2]), "+f"(d[3])
        : "r"(a[0]), "r"(a[1]), "r"(a[2]), "r"(a[3]), "r"(b[0]), "r"(b[1]));
}

// smem: 3 matrices (A, Bh, Bl), 128 rows x 64 fp16, padded row = 144B
#define ROWB   144
#define MATB   (128*ROWB)        // 18432
#define STAGEB (3*MATB)          // 55296
#define SMEM_REQ (2*STAGEB)      // 110592

// ============================================================================
// prep: x fp32 -> fp16 (8 elems/thread)
__global__ __launch_bounds__(256) void k_split(const float* __restrict__ x)
{
    size_t i = ((size_t)blockIdx.x * 256 + threadIdx.x) * 8;
    float4 a = *(const float4*)(x + i);
    float4 b = *(const float4*)(x + i + 4);
    __half2* o = (__half2*)(g_x + i);
    o[0] = __floats2half2_rn(a.x, a.y);
    o[1] = __floats2half2_rn(a.z, a.w);
    o[2] = __floats2half2_rn(b.x, b.y);
    o[3] = __floats2half2_rn(b.z, b.w);
}

// prep: w[z][K][N] fp32 -> hi/lo[z][N][K] fp16, scaled by WSCALE
__global__ __launch_bounds__(256) void k_trans(const float* __restrict__ w,
                                               __half* __restrict__ hi,
                                               __half* __restrict__ lo,
                                               int K, int N)
{
    __shared__ float s[64][33];
    int z = blockIdx.z;
    const float* wz = w + (size_t)z * K * N;
    __half* hz = hi + (size_t)z * K * N;
    __half* lz = lo + (size_t)z * K * N;
    int n0 = blockIdx.x * 32, k0 = blockIdx.y * 64;
    int tid = threadIdx.x;

    {
        int row = tid >> 3, q = tid & 7;
#pragma unroll
        for (int it = 0; it < 2; it++) {
            // vector global load, SCALAR smem stores (stride 33 is not 16B-aligned)
            float4 v = *(const float4*)(wz + (size_t)(k0 + row + it * 32) * N + n0 + q * 4);
            float* sp = &s[row + it * 32][q * 4];
            sp[0] = v.x; sp[1] = v.y; sp[2] = v.z; sp[3] = v.w;
        }
    }
    __syncthreads();

    int n = tid >> 3, kseg = tid & 7;
    __align__(16) __half hbuf[8];
    __align__(16) __half lbuf[8];
#pragma unroll
    for (int u = 0; u < 8; u++) {
        float v = s[kseg * 8 + u][n] * WSCALE;
        __half h = __float2half_rn(v);
        hbuf[u] = h;
        lbuf[u] = __float2half_rn(v - __half2float(h));
    }
    size_t off = (size_t)(n0 + n) * K + k0 + kseg * 8;
    *(uint4*)(hz + off) = *(uint4*)hbuf;
    *(uint4*)(lz + off) = *(uint4*)lbuf;
}

// ============================================================================
// gate
__global__ __launch_bounds__(256) void k_gate(const float* __restrict__ x,
                                              const float* __restrict__ gw,
                                              const float* __restrict__ gb,
                                              float* __restrict__ ew_out)
{
    __shared__ float s_gw[D_IN * NEXP];
    int tid = threadIdx.x;
    for (int i = tid; i < (D_IN * NEXP) / 4; i += 256)
        ((float4*)s_gw)[i] = ((const float4*)gw)[i];
    __syncthreads();
    int warp = tid >> 5, lane = tid & 31;
    int t = blockIdx.x * 8 + warp;
    const float* xr = x + (size_t)t * D_IN;
    float acc[NEXP];
#pragma unroll
    for (int e = 0; e < NEXP; e++) acc[e] = 0.f;
    for (int d = lane; d < D_IN; d += 32) {
        float xv = xr[d];
        float4 g0 = *(const float4*)&s_gw[d * 8];
        float4 g1 = *(const float4*)&s_gw[d * 8 + 4];
        acc[0] += xv * g0.x; acc[1] += xv * g0.y; acc[2] += xv * g0.z; acc[3] += xv * g0.w;
        acc[4] += xv * g1.x; acc[5] += xv * g1.y; acc[6] += xv * g1.z; acc[7] += xv * g1.w;
    }
#pragma unroll
    for (int off = 16; off > 0; off >>= 1)
#pragma unroll
        for (int e = 0; e < NEXP; e++) acc[e] += __shfl_down_sync(0xffffffffu, acc[e], off);
    if (lane == 0) {
        float l[NEXP], m = -1e30f;
#pragma unroll
        for (int e = 0; e < NEXP; e++) { l[e] = acc[e] + gb[e]; m = fmaxf(m, l[e]); }
        float s = 0.f;
#pragma unroll
        for (int e = 0; e < NEXP; e++) { l[e] = expf(l[e] - m); s += l[e]; }
        float inv = 1.f / s;
#pragma unroll
        for (int e = 0; e < NEXP; e++) { l[e] *= inv; ew_out[(size_t)t * NEXP + e] = l[e]; }
        int i0 = 0;
#pragma unroll
        for (int e = 1; e < NEXP; e++) if (l[e] > l[i0]) i0 = e;
        int i1 = (i0 == 0) ? 1 : 0;
#pragma unroll
        for (int e = 0; e < NEXP; e++) if (e != i0 && l[e] > l[i1]) i1 = e;
        float v0 = l[i0], v1 = l[i1], r = 1.f / (v0 + v1);
        g_topi[t * 2 + 0] = i0; g_topv[t * 2 + 0] = v0 * r;
        g_topi[t * 2 + 1] = i1; g_topv[t * 2 + 1] = v1 * r;
    }
}

// sort
__global__ __launch_bounds__(1024) void k_sort()
{
    __shared__ int s_cnt[NEXP][1024];
    __shared__ int s_seg[NEXP + 1];
    int tid = threadIdx.x;
    for (int i = tid; i < MAXROWS; i += 1024) { g_row_token[i] = -1; g_row_weight[i] = 0.f; }
    int own[NEXP];
#pragma unroll
    for (int e = 0; e < NEXP; e++) own[e] = 0;
    int base_a = tid * 16;
#pragma unroll
    for (int j = 0; j < 16; j++) own[g_topi[base_a + j]]++;
#pragma unroll
    for (int e = 0; e < NEXP; e++) s_cnt[e][tid] = own[e];
    __syncthreads();
    for (int off = 1; off < 1024; off <<= 1) {
        int v[NEXP];
#pragma unroll
        for (int e = 0; e < NEXP; e++) v[e] = (tid >= off) ? s_cnt[e][tid - off] : 0;
        __syncthreads();
#pragma unroll
        for (int e = 0; e < NEXP; e++) s_cnt[e][tid] += v[e];
        __syncthreads();
    }
    if (tid == 0) {
        int s = 0;
        for (int e = 0; e < NEXP; e++) {
            s_seg[e] = s;
            s += ((s_cnt[e][1023] + 127) / 128) * 128;
        }
        s_seg[NEXP] = s;
    }
    __syncthreads();
    int base[NEXP];
#pragma unroll
    for (int e = 0; e < NEXP; e++) base[e] = s_seg[e] + s_cnt[e][tid] - own[e];
#pragma unroll
    for (int j = 0; j < 16; j++) {
        int a = base_a + j, e = g_topi[a], pos = base[e]++;
        g_row_token[pos] = a >> 1;
        g_row_weight[pos] = g_topv[a];
        g_slot[a] = pos;
    }
    for (int i = tid; i < NTILES; i += 1024) {
        int rs = i * 128, ee = 0;
        for (int q = 0; q < NEXP; q++) if (rs >= s_seg[q + 1]) ee = q + 1;
        g_tile_expert[i] = (rs < s_seg[NEXP] && ee < NEXP) ? ee : 0;
    }
}

// ============================================================================
// HMMA GEMM fp16 2-term: D = A * (Bh + Bl)^T * (1/32)
// 128x128 CTA tile, BK=64, 8 warps (2x4), warp tile 64x32
template<int MODE>
__global__ __launch_bounds__(256) void k_gemm(
    const __half* __restrict__ A,
    const __half* __restrict__ Bh, const __half* __restrict__ Bl,
    const float* __restrict__ bias, int Ktot, int Nout,
    __half* __restrict__ outh, float* __restrict__ outf)
{
    extern __shared__ char dsm[];
    __shared__ int s_tok[128];
    uint32_t sb = smem_u32(dsm);

    int tid = threadIdx.x, bm = blockIdx.x, bn = blockIdx.y;
    int warp = tid >> 5, lane = tid & 31;
    int wm = warp >> 2, wn = warp & 3;

    if (MODE <= 1) {
        int e = g_tile_expert[bm];
        size_t wo = (size_t)e * Nout * Ktot;
        Bh += wo; Bl += wo; bias += (size_t)e * Nout;
    }
    if (tid < 128) {
        int r = bm * 128 + tid;
        s_tok[tid] = (MODE == 0) ? g_row_token[r] : r;
    }
    __syncthreads();

    float acc[4][4][4];
#pragma unroll
    for (int i = 0; i < 4; i++)
#pragma unroll
        for (int j = 0; j < 4; j++)
#pragma unroll
            for (int q = 0; q < 4; q++) acc[i][j][q] = 0.f;

    const int nc = Ktot >> 6;                    // chunks of K=64

    auto issue = [&](int c, int st) {
        int kel = c * 64;
        uint32_t base = sb + st * STAGEB;
#pragma unroll
        for (int it = 0; it < 12; it++) {
            int p = tid + it * 256;              // 0..3071
            int mat = p >> 10, r = (p >> 3) & 127, seg = p & 7;
            uint32_t dst = base + mat * MATB + r * ROWB + seg * 16;
            if (mat == 0) {
                int tok = s_tok[r];
                int sz = (tok >= 0) ? 16 : 0;
                int tr = (tok >= 0) ? tok : 0;
                cp16(dst, A + (size_t)tr * Ktot + kel + seg * 8, sz);
            } else {
                const __half* src =
                    (mat == 2 ? Bl : Bh) + (size_t)(bn * 128 + r) * Ktot + kel + seg * 8;
                cp16(dst, src, 16);
            }
        }
    };

    issue(0, 0);
    cp_commit();

    for (int c = 0; c < nc; c++) {
        if (c + 1 < nc) { issue(c + 1, (c + 1) & 1); cp_commit(); cp_wait1(); }
        else cp_wait0();
        __syncthreads();

        uint32_t st = sb + (c & 1) * STAGEB;
#pragma unroll
        for (int h = 0; h < 4; h++) {
            int ks = h * 16;
            uint32_t fA[4][4];
            {
                int row = wm * 64 + (lane & 15);
                int col = ks + (lane >> 4) * 8;
                uint32_t off = (uint32_t)row * ROWB + col * 2;
#pragma unroll
                for (int mt = 0; mt < 4; mt++)
                    ldm_x4(fA[mt], st + off + mt * 16 * ROWB);
            }
            uint32_t fBh[4][2], fBl[4][2];
            {
                int nr = wn * 32 + (lane & 7) + (lane >> 4) * 8;
                int kc = ks + ((lane >> 3) & 1) * 8;
                uint32_t off = (uint32_t)nr * ROWB + kc * 2;
#pragma unroll
                for (int bt = 0; bt < 2; bt++) {
                    uint32_t t4[4];
                    ldm_x4(t4, st + MATB + off + bt * 16 * ROWB);
                    fBh[bt * 2][0] = t4[0]; fBh[bt * 2][1] = t4[1];
                    fBh[bt * 2 + 1][0] = t4[2]; fBh[bt * 2 + 1][1] = t4[3];
                    ldm_x4(t4, st + 2 * MATB + off + bt * 16 * ROWB);
                    fBl[bt * 2][0] = t4[0]; fBl[bt * 2][1] = t4[1];
                    fBl[bt * 2 + 1][0] = t4[2]; fBl[bt * 2 + 1][1] = t4[3];
                }
            }
#pragma unroll
            for (int mt = 0; mt < 4; mt++)
#pragma unroll
                for (int nt = 0; nt < 4; nt++) {
                    mma_f16(acc[mt][nt], fA[mt], fBh[nt]);
                    mma_f16(acc[mt][nt], fA[mt], fBl[nt]);
                }
        }
        __syncthreads();
    }

    // -------- epilogue (unscale by 1/32, then bias) --------
    int mg = lane >> 2;
    int cp = 2 * (lane & 3);
#pragma unroll
    for (int mt = 0; mt < 4; mt++) {
#pragma unroll
        for (int rr = 0; rr < 2; rr++) {
            int row = bm * 128 + wm * 64 + mt * 16 + mg + rr * 8;
            float wgt = 0.f;
            const float *e0 = 0, *e1 = 0;
            if (MODE == 1) wgt = g_row_weight[row];
            if (MODE == 3) {
                e0 = g_eo + (size_t)g_slot[row * 2 + 0] * D_OUT;
                e1 = g_eo + (size_t)g_slot[row * 2 + 1] * D_OUT;
            }
#pragma unroll
            for (int nt = 0; nt < 4; nt++) {
                int n = bn * 128 + wn * 32 + nt * 8 + cp;
                float c0 = acc[mt][nt][rr * 2 + 0] * WSCALE_INV;
                float c1 = acc[mt][nt][rr * 2 + 1] * WSCALE_INV;
                float2 bv = *(const float2*)&bias[n];
                if (MODE == 0 || MODE == 2) {
                    float v0 = fmaxf(c0 + bv.x, 0.f);
                    float v1 = fmaxf(c1 + bv.y, 0.f);
                    *(__half2*)(outh + (size_t)row * Nout + n) = __floats2half2_rn(v0, v1);
                } else if (MODE == 1) {
                    float2 o;
                    o.x = wgt * (c0 + bv.x);
                    o.y = wgt * (c1 + bv.y);
                    *(float2*)(outf + (size_t)row * Nout + n) = o;
                } else {
                    float2 a = *(const float2*)(e0 + n);
                    float2 b = *(const float2*)(e1 + n);
                    float2 o;
                    o.x = c0 + bv.x + a.x + b.x;
                    o.y = c1 + bv.y + a.y + b.y;
                    *(float2*)(outf + (size_t)row * Nout + n) = o;
                }
            }
        }
    }
}

// ============================================================================
extern "C" void kernel_launch(void* const* d_in, const int* in_sizes, int n_in,
                              void* d_out, int out_size)
{
    const float* x      = (const float*)d_in[0];
    const float* gate_w = (const float*)d_in[1];
    const float* gate_b = (const float*)d_in[2];
    const float* ew1    = (const float*)d_in[3];
    const float* eb1    = (const float*)d_in[4];
    const float* ew2    = (const float*)d_in[5];
    const float* eb2    = (const float*)d_in[6];
    const float* sw1    = (const float*)d_in[7];
    const float* sb1    = (const float*)d_in[8];
    const float* sw2    = (const float*)d_in[9];
    const float* sb2    = (const float*)d_in[10];
    (void)in_sizes; (void)n_in; (void)out_size;

    float* out    = (float*)d_out;
    float* ew_out = out + (size_t)T_TOK * D_OUT;

    cudaFuncSetAttribute(k_gemm<0>, cudaFuncAttributeMaxDynamicSharedMemorySize, SMEM_REQ);
    cudaFuncSetAttribute(k_gemm<1>, cudaFuncAttributeMaxDynamicSharedMemorySize, SMEM_REQ);
    cudaFuncSetAttribute(k_gemm<2>, cudaFuncAttributeMaxDynamicSharedMemorySize, SMEM_REQ);
    cudaFuncSetAttribute(k_gemm<3>, cudaFuncAttributeMaxDynamicSharedMemorySize, SMEM_REQ);

    __half *xh, *w1h, *w1l, *w2h, *w2l, *s1h, *s1l, *s2h, *s2l, *hh, *hsh;
    cudaGetSymbolAddress((void**)&xh,  g_x);
    cudaGetSymbolAddress((void**)&w1h, g_w1t_hi); cudaGetSymbolAddress((void**)&w1l, g_w1t_lo);
    cudaGetSymbolAddress((void**)&w2h, g_w2t_hi); cudaGetSymbolAddress((void**)&w2l, g_w2t_lo);
    cudaGetSymbolAddress((void**)&s1h, g_s1t_hi); cudaGetSymbolAddress((void**)&s1l, g_s1t_lo);
    cudaGetSymbolAddress((void**)&s2h, g_s2t_hi); cudaGetSymbolAddress((void**)&s2l, g_s2t_lo);
    cudaGetSymbolAddress((void**)&hh,  g_h);      cudaGetSymbolAddress((void**)&hsh, g_hs);
    float* eo;
    cudaGetSymbolAddress((void**)&eo, g_eo);

    // prep
    k_split<<<(T_TOK * D_IN) / 2048, 256>>>(x);
    k_trans<<<dim3(HID/32,   D_IN/64, NEXP), 256>>>(ew1, w1h, w1l, D_IN, HID);
    k_trans<<<dim3(D_OUT/32, HID/64,  NEXP), 256>>>(ew2, w2h, w2l, HID, D_OUT);
    k_trans<<<dim3(HID/32,   D_IN/64, 1),    256>>>(sw1, s1h, s1l, D_IN, HID);
    k_trans<<<dim3(D_OUT/32, HID/64,  1),    256>>>(sw2, s2h, s2l, HID, D_OUT);

    k_gate<<<T_TOK / 8, 256>>>(x, gate_w, gate_b, ew_out);
    k_sort<<<1, 1024>>>();

    k_gemm<0><<<dim3(NTILES, HID/128),      256, SMEM_REQ>>>(xh,  w1h, w1l, eb1, D_IN, HID,  hh,  0);
    k_gemm<1><<<dim3(NTILES, D_OUT/128),    256, SMEM_REQ>>>(hh,  w2h, w2l, eb2, HID, D_OUT, 0,   eo);
    k_gemm<2><<<dim3(T_TOK/128, HID/128),   256, SMEM_REQ>>>(xh,  s1h, s1l, sb1, D_IN, HID,  hsh, 0);
    k_gemm<3><<<dim3(T_TOK/128, D_OUT/128), 256, SMEM_REQ>>>(hsh, s2h, s2l, sb2, HID, D_OUT, 0,   out);
}

// round 11
// speedup vs baseline: 1.5347x; 1.5347x over previous
#include <cuda_runtime.h>
#include <cuda_fp16.h>
#include <math.h>
#include <stdint.h>

#define T_TOK   8192
#define D_IN    1024
#define HID     2048
#define D_OUT   1024
#define NEXP    8
#define MAXROWS 17408
#define NTILES  (MAXROWS/128)   // 136
#define WSCALE     32.0f
#define WSCALE_INV 0.03125f

// ---------------- scratch (16B-access targets are 256B aligned) ----------------
__device__ int   g_topi[T_TOK * 2];
__device__ float g_topv[T_TOK * 2];
__device__ int   g_row_token[MAXROWS];
__device__ float g_row_weight[MAXROWS];
__device__ int   g_slot[T_TOK * 2];
__device__ int   g_tile_expert[NTILES];
__device__ __align__(256) float g_eo[(size_t)MAXROWS * D_OUT];
__device__ __align__(256) __half g_x  [(size_t)T_TOK   * D_IN];
__device__ __align__(256) __half g_h  [(size_t)MAXROWS * HID];
__device__ __align__(256) __half g_hs [(size_t)T_TOK   * HID];
__device__ __align__(256) __half g_w1t_hi[(size_t)NEXP * HID * D_IN];
__device__ __align__(256) __half g_w1t_lo[(size_t)NEXP * HID * D_IN];
__device__ __align__(256) __half g_w2t_hi[(size_t)NEXP * D_OUT * HID];
__device__ __align__(256) __half g_w2t_lo[(size_t)NEXP * D_OUT * HID];
__device__ __align__(256) __half g_s1t_hi[(size_t)HID * D_IN];
__device__ __align__(256) __half g_s1t_lo[(size_t)HID * D_IN];
__device__ __align__(256) __half g_s2t_hi[(size_t)D_OUT * HID];
__device__ __align__(256) __half g_s2t_lo[(size_t)D_OUT * HID];

// ---------------- helpers (base-ISA: cp.async, ldmatrix, mma.sync) ----------
__device__ __forceinline__ uint32_t smem_u32(const void* p) {
    uint32_t a;
    asm("{ .reg .u64 t; cvta.to.shared.u64 t, %1; cvt.u32.u64 %0, t; }" : "=r"(a) : "l"(p));
    return a;
}
__device__ __forceinline__ void cp16(uint32_t s, const void* g, int srcsz) {
    asm volatile("cp.async.cg.shared.global [%0], [%1], 16, %2;" :: "r"(s), "l"(g), "r"(srcsz));
}
__device__ __forceinline__ void cp_commit() { asm volatile("cp.async.commit_group;" ::: "memory"); }
__device__ __forceinline__ void cp_wait1()  { asm volatile("cp.async.wait_group 1;" ::: "memory"); }
__device__ __forceinline__ void cp_wait0()  { asm volatile("cp.async.wait_group 0;" ::: "memory"); }
__device__ __forceinline__ void ldm_x4(uint32_t* r, uint32_t addr) {
    asm volatile("ldmatrix.sync.aligned.m8n8.x4.shared.b16 {%0,%1,%2,%3}, [%4];"
                 : "=r"(r[0]), "=r"(r[1]), "=r"(r[2]), "=r"(r[3]) : "r"(addr));
}
__device__ __forceinline__ void mma_f16(float* d, const uint32_t* a, const uint32_t* b) {
    asm volatile(
        "mma.sync.aligned.m16n8k16.row.col.f32.f16.f16.f32 "
        "{%0,%1,%2,%3}, {%4,%5,%6,%7}, {%8,%9}, {%0,%1,%2,%3};"
        : "+f"(d[0]), "+f"(d[1]), "+f"(d[2]), "+f"(d[3])
        : "r"(a[0]), "r"(a[1]), "r"(a[2]), "r"(a[3]), "r"(b[0]), "r"(b[1]));
}

// smem: 3 matrices (A, Bh, Bl), 128 rows x 64 fp16, padded row = 144B
#define ROWB   144
#define MATB   (128*ROWB)        // 18432
#define STAGEB (3*MATB)          // 55296
#define SMEM_REQ (2*STAGEB)      // 110592

// ============================================================================
// prep: x fp32 -> fp16 (8 elems/thread)
__global__ __launch_bounds__(256) void k_split(const float* __restrict__ x)
{
    size_t i = ((size_t)blockIdx.x * 256 + threadIdx.x) * 8;
    float4 a = *(const float4*)(x + i);
    float4 b = *(const float4*)(x + i + 4);
    __half2* o = (__half2*)(g_x + i);
    o[0] = __floats2half2_rn(a.x, a.y);
    o[1] = __floats2half2_rn(a.z, a.w);
    o[2] = __floats2half2_rn(b.x, b.y);
    o[3] = __floats2half2_rn(b.z, b.w);
}

// prep: w[z][K][N] fp32 -> hi/lo[z][N][K] fp16, scaled by WSCALE
__global__ __launch_bounds__(256) void k_trans(const float* __restrict__ w,
                                               __half* __restrict__ hi,
                                               __half* __restrict__ lo,
                                               int K, int N)
{
    __shared__ float s[64][33];
    int z = blockIdx.z;
    const float* wz = w + (size_t)z * K * N;
    __half* hz = hi + (size_t)z * K * N;
    __half* lz = lo + (size_t)z * K * N;
    int n0 = blockIdx.x * 32, k0 = blockIdx.y * 64;
    int tid = threadIdx.x;

    {
        int row = tid >> 3, q = tid & 7;
#pragma unroll
        for (int it = 0; it < 2; it++) {
            // vector global load, SCALAR smem stores (stride 33 is not 16B-aligned)
            float4 v = *(const float4*)(wz + (size_t)(k0 + row + it * 32) * N + n0 + q * 4);
            float* sp = &s[row + it * 32][q * 4];
            sp[0] = v.x; sp[1] = v.y; sp[2] = v.z; sp[3] = v.w;
        }
    }
    __syncthreads();

    int n = tid >> 3, kseg = tid & 7;
    __align__(16) __half hbuf[8];
    __align__(16) __half lbuf[8];
#pragma unroll
    for (int u = 0; u < 8; u++) {
        float v = s[kseg * 8 + u][n] * WSCALE;
        __half h = __float2half_rn(v);
        hbuf[u] = h;
        lbuf[u] = __float2half_rn(v - __half2float(h));
    }
    size_t off = (size_t)(n0 + n) * K + k0 + kseg * 8;
    *(uint4*)(hz + off) = *(uint4*)hbuf;
    *(uint4*)(lz + off) = *(uint4*)lbuf;
}

// ============================================================================
// gate
__global__ __launch_bounds__(256) void k_gate(const float* __restrict__ x,
                                              const float* __restrict__ gw,
                                              const float* __restrict__ gb,
                                              float* __restrict__ ew_out)
{
    __shared__ float s_gw[D_IN * NEXP];
    int tid = threadIdx.x;
    for (int i = tid; i < (D_IN * NEXP) / 4; i += 256)
        ((float4*)s_gw)[i] = ((const float4*)gw)[i];
    __syncthreads();
    int warp = tid >> 5, lane = tid & 31;
    int t = blockIdx.x * 8 + warp;
    const float* xr = x + (size_t)t * D_IN;
    float acc[NEXP];
#pragma unroll
    for (int e = 0; e < NEXP; e++) acc[e] = 0.f;
    for (int d = lane; d < D_IN; d += 32) {
        float xv = xr[d];
        float4 g0 = *(const float4*)&s_gw[d * 8];
        float4 g1 = *(const float4*)&s_gw[d * 8 + 4];
        acc[0] += xv * g0.x; acc[1] += xv * g0.y; acc[2] += xv * g0.z; acc[3] += xv * g0.w;
        acc[4] += xv * g1.x; acc[5] += xv * g1.y; acc[6] += xv * g1.z; acc[7] += xv * g1.w;
    }
#pragma unroll
    for (int off = 16; off > 0; off >>= 1)
#pragma unroll
        for (int e = 0; e < NEXP; e++) acc[e] += __shfl_down_sync(0xffffffffu, acc[e], off);
    if (lane == 0) {
        float l[NEXP], m = -1e30f;
#pragma unroll
        for (int e = 0; e < NEXP; e++) { l[e] = acc[e] + gb[e]; m = fmaxf(m, l[e]); }
        float s = 0.f;
#pragma unroll
        for (int e = 0; e < NEXP; e++) { l[e] = expf(l[e] - m); s += l[e]; }
        float inv = 1.f / s;
#pragma unroll
        for (int e = 0; e < NEXP; e++) { l[e] *= inv; ew_out[(size_t)t * NEXP + e] = l[e]; }
        int i0 = 0;
#pragma unroll
        for (int e = 1; e < NEXP; e++) if (l[e] > l[i0]) i0 = e;
        int i1 = (i0 == 0) ? 1 : 0;
#pragma unroll
        for (int e = 0; e < NEXP; e++) if (e != i0 && l[e] > l[i1]) i1 = e;
        float v0 = l[i0], v1 = l[i1], r = 1.f / (v0 + v1);
        g_topi[t * 2 + 0] = i0; g_topv[t * 2 + 0] = v0 * r;
        g_topi[t * 2 + 1] = i1; g_topv[t * 2 + 1] = v1 * r;
    }
}

// sort
__global__ __launch_bounds__(1024) void k_sort()
{
    __shared__ int s_cnt[NEXP][1024];
    __shared__ int s_seg[NEXP + 1];
    int tid = threadIdx.x;
    for (int i = tid; i < MAXROWS; i += 1024) { g_row_token[i] = -1; g_row_weight[i] = 0.f; }
    int own[NEXP];
#pragma unroll
    for (int e = 0; e < NEXP; e++) own[e] = 0;
    int base_a = tid * 16;
#pragma unroll
    for (int j = 0; j < 16; j++) own[g_topi[base_a + j]]++;
#pragma unroll
    for (int e = 0; e < NEXP; e++) s_cnt[e][tid] = own[e];
    __syncthreads();
    for (int off = 1; off < 1024; off <<= 1) {
        int v[NEXP];
#pragma unroll
        for (int e = 0; e < NEXP; e++) v[e] = (tid >= off) ? s_cnt[e][tid - off] : 0;
        __syncthreads();
#pragma unroll
        for (int e = 0; e < NEXP; e++) s_cnt[e][tid] += v[e];
        __syncthreads();
    }
    if (tid == 0) {
        int s = 0;
        for (int e = 0; e < NEXP; e++) {
            s_seg[e] = s;
            s += ((s_cnt[e][1023] + 127) / 128) * 128;
        }
        s_seg[NEXP] = s;
    }
    __syncthreads();
    int base[NEXP];
#pragma unroll
    for (int e = 0; e < NEXP; e++) base[e] = s_seg[e] + s_cnt[e][tid] - own[e];
#pragma unroll
    for (int j = 0; j < 16; j++) {
        int a = base_a + j, e = g_topi[a], pos = base[e]++;
        g_row_token[pos] = a >> 1;
        g_row_weight[pos] = g_topv[a];
        g_slot[a] = pos;
    }
    for (int i = tid; i < NTILES; i += 1024) {
        int rs = i * 128, ee = 0;
        for (int q = 0; q < NEXP; q++) if (rs >= s_seg[q + 1]) ee = q + 1;
        g_tile_expert[i] = (rs < s_seg[NEXP] && ee < NEXP) ? ee : 0;
    }
}

// ============================================================================
// HMMA GEMM fp16 2-term: D = A * (Bh + Bl)^T * (1/32)
// 128x128 CTA tile, BK=64, 8 warps (2x4), warp tile 64x32
template<int MODE>
__global__ __launch_bounds__(256) void k_gemm(
    const __half* __restrict__ A,
    const __half* __restrict__ Bh, const __half* __restrict__ Bl,
    const float* __restrict__ bias, int Ktot, int Nout,
    __half* __restrict__ outh, float* __restrict__ outf)
{
    extern __shared__ char dsm[];
    __shared__ int s_tok[128];
    uint32_t sb = smem_u32(dsm);

    int tid = threadIdx.x, bm = blockIdx.x, bn = blockIdx.y;
    int warp = tid >> 5, lane = tid & 31;
    int wm = warp >> 2, wn = warp & 3;

    if (MODE <= 1) {
        int e = g_tile_expert[bm];
        size_t wo = (size_t)e * Nout * Ktot;
        Bh += wo; Bl += wo; bias += (size_t)e * Nout;
    }
    if (tid < 128) {
        int r = bm * 128 + tid;
        s_tok[tid] = (MODE == 0) ? g_row_token[r] : r;
    }
    __syncthreads();

    float acc[4][4][4];
#pragma unroll
    for (int i = 0; i < 4; i++)
#pragma unroll
        for (int j = 0; j < 4; j++)
#pragma unroll
            for (int q = 0; q < 4; q++) acc[i][j][q] = 0.f;

    const int nc = Ktot >> 6;                    // chunks of K=64

    auto issue = [&](int c, int st) {
        int kel = c * 64;
        uint32_t base = sb + st * STAGEB;
#pragma unroll
        for (int it = 0; it < 12; it++) {
            int p = tid + it * 256;              // 0..3071
            int mat = p >> 10, r = (p >> 3) & 127, seg = p & 7;
            uint32_t dst = base + mat * MATB + r * ROWB + seg * 16;
            if (mat == 0) {
                int tok = s_tok[r];
                int sz = (tok >= 0) ? 16 : 0;
                int tr = (tok >= 0) ? tok : 0;
                cp16(dst, A + (size_t)tr * Ktot + kel + seg * 8, sz);
            } else {
                const __half* src =
                    (mat == 2 ? Bl : Bh) + (size_t)(bn * 128 + r) * Ktot + kel + seg * 8;
                cp16(dst, src, 16);
            }
        }
    };

    issue(0, 0);
    cp_commit();

    for (int c = 0; c < nc; c++) {
        if (c + 1 < nc) { issue(c + 1, (c + 1) & 1); cp_commit(); cp_wait1(); }
        else cp_wait0();
        __syncthreads();

        uint32_t st = sb + (c & 1) * STAGEB;
#pragma unroll
        for (int h = 0; h < 4; h++) {
            int ks = h * 16;
            uint32_t fA[4][4];
            {
                int row = wm * 64 + (lane & 15);
                int col = ks + (lane >> 4) * 8;
                uint32_t off = (uint32_t)row * ROWB + col * 2;
#pragma unroll
                for (int mt = 0; mt < 4; mt++)
                    ldm_x4(fA[mt], st + off + mt * 16 * ROWB);
            }
            uint32_t fBh[4][2], fBl[4][2];
            {
                int nr = wn * 32 + (lane & 7) + (lane >> 4) * 8;
                int kc = ks + ((lane >> 3) & 1) * 8;
                uint32_t off = (uint32_t)nr * ROWB + kc * 2;
#pragma unroll
                for (int bt = 0; bt < 2; bt++) {
                    uint32_t t4[4];
                    ldm_x4(t4, st + MATB + off + bt * 16 * ROWB);
                    fBh[bt * 2][0] = t4[0]; fBh[bt * 2][1] = t4[1];
                    fBh[bt * 2 + 1][0] = t4[2]; fBh[bt * 2 + 1][1] = t4[3];
                    ldm_x4(t4, st + 2 * MATB + off + bt * 16 * ROWB);
                    fBl[bt * 2][0] = t4[0]; fBl[bt * 2][1] = t4[1];
                    fBl[bt * 2 + 1][0] = t4[2]; fBl[bt * 2 + 1][1] = t4[3];
                }
            }
#pragma unroll
            for (int mt = 0; mt < 4; mt++)
#pragma unroll
                for (int nt = 0; nt < 4; nt++) {
                    mma_f16(acc[mt][nt], fA[mt], fBh[nt]);
                    mma_f16(acc[mt][nt], fA[mt], fBl[nt]);
                }
        }
        __syncthreads();
    }

    // -------- epilogue (unscale by 1/32, then bias) --------
    int mg = lane >> 2;
    int cp = 2 * (lane & 3);
#pragma unroll
    for (int mt = 0; mt < 4; mt++) {
#pragma unroll
        for (int rr = 0; rr < 2; rr++) {
            int row = bm * 128 + wm * 64 + mt * 16 + mg + rr * 8;
            float wgt = 0.f;
            const float *e0 = 0, *e1 = 0;
            if (MODE == 1) wgt = g_row_weight[row];
            if (MODE == 3) {
                e0 = g_eo + (size_t)g_slot[row * 2 + 0] * D_OUT;
                e1 = g_eo + (size_t)g_slot[row * 2 + 1] * D_OUT;
            }
#pragma unroll
            for (int nt = 0; nt < 4; nt++) {
                int n = bn * 128 + wn * 32 + nt * 8 + cp;
                float c0 = acc[mt][nt][rr * 2 + 0] * WSCALE_INV;
                float c1 = acc[mt][nt][rr * 2 + 1] * WSCALE_INV;
                float2 bv = *(const float2*)&bias[n];
                if (MODE == 0 || MODE == 2) {
                    float v0 = fmaxf(c0 + bv.x, 0.f);
                    float v1 = fmaxf(c1 + bv.y, 0.f);
                    *(__half2*)(outh + (size_t)row * Nout + n) = __floats2half2_rn(v0, v1);
                } else if (MODE == 1) {
                    float2 o;
                    o.x = wgt * (c0 + bv.x);
                    o.y = wgt * (c1 + bv.y);
                    *(float2*)(outf + (size_t)row * Nout + n) = o;
                } else {
                    float2 a = *(const float2*)(e0 + n);
                    float2 b = *(const float2*)(e1 + n);
                    float2 o;
                    o.x = c0 + bv.x + a.x + b.x;
                    o.y = c1 + bv.y + a.y + b.y;
                    *(float2*)(outf + (size_t)row * Nout + n) = o;
                }
            }
        }
    }
}

// ============================================================================
extern "C" void kernel_launch(void* const* d_in, const int* in_sizes, int n_in,
                              void* d_out, int out_size)
{
    const float* x      = (const float*)d_in[0];
    const float* gate_w = (const float*)d_in[1];
    const float* gate_b = (const float*)d_in[2];
    const float* ew1    = (const float*)d_in[3];
    const float* eb1    = (const float*)d_in[4];
    const float* ew2    = (const float*)d_in[5];
    const float* eb2    = (const float*)d_in[6];
    const float* sw1    = (const float*)d_in[7];
    const float* sb1    = (const float*)d_in[8];
    const float* sw2    = (const float*)d_in[9];
    const float* sb2    = (const float*)d_in[10];
    (void)in_sizes; (void)n_in; (void)out_size;

    float* out    = (float*)d_out;
    float* ew_out = out + (size_t)T_TOK * D_OUT;

    cudaFuncSetAttribute(k_gemm<0>, cudaFuncAttributeMaxDynamicSharedMemorySize, SMEM_REQ);
    cudaFuncSetAttribute(k_gemm<1>, cudaFuncAttributeMaxDynamicSharedMemorySize, SMEM_REQ);
    cudaFuncSetAttribute(k_gemm<2>, cudaFuncAttributeMaxDynamicSharedMemorySize, SMEM_REQ);
    cudaFuncSetAttribute(k_gemm<3>, cudaFuncAttributeMaxDynamicSharedMemorySize, SMEM_REQ);

    __half *xh, *w1h, *w1l, *w2h, *w2l, *s1h, *s1l, *s2h, *s2l, *hh, *hsh;
    cudaGetSymbolAddress((void**)&xh,  g_x);
    cudaGetSymbolAddress((void**)&w1h, g_w1t_hi); cudaGetSymbolAddress((void**)&w1l, g_w1t_lo);
    cudaGetSymbolAddress((void**)&w2h, g_w2t_hi); cudaGetSymbolAddress((void**)&w2l, g_w2t_lo);
    cudaGetSymbolAddress((void**)&s1h, g_s1t_hi); cudaGetSymbolAddress((void**)&s1l, g_s1t_lo);
    cudaGetSymbolAddress((void**)&s2h, g_s2t_hi); cudaGetSymbolAddress((void**)&s2l, g_s2t_lo);
    cudaGetSymbolAddress((void**)&hh,  g_h);      cudaGetSymbolAddress((void**)&hsh, g_hs);
    float* eo;
    cudaGetSymbolAddress((void**)&eo, g_eo);

    // prep
    k_split<<<(T_TOK * D_IN) / 2048, 256>>>(x);
    k_trans<<<dim3(HID/32,   D_IN/64, NEXP), 256>>>(ew1, w1h, w1l, D_IN, HID);
    k_trans<<<dim3(D_OUT/32, HID/64,  NEXP), 256>>>(ew2, w2h, w2l, HID, D_OUT);
    k_trans<<<dim3(HID/32,   D_IN/64, 1),    256>>>(sw1, s1h, s1l, D_IN, HID);
    k_trans<<<dim3(D_OUT/32, HID/64,  1),    256>>>(sw2, s2h, s2l, HID, D_OUT);

    k_gate<<<T_TOK / 8, 256>>>(x, gate_w, gate_b, ew_out);
    k_sort<<<1, 1024>>>();

    k_gemm<0><<<dim3(NTILES, HID/128),      256, SMEM_REQ>>>(xh,  w1h, w1l, eb1, D_IN, HID,  hh,  0);
    k_gemm<1><<<dim3(NTILES, D_OUT/128),    256, SMEM_REQ>>>(hh,  w2h, w2l, eb2, HID, D_OUT, 0,   eo);
    k_gemm<2><<<dim3(T_TOK/128, HID/128),   256, SMEM_REQ>>>(xh,  s1h, s1l, sb1, D_IN, HID,  hsh, 0);
    k_gemm<3><<<dim3(T_TOK/128, D_OUT/128), 256, SMEM_REQ>>>(hsh, s2h, s2l, sb2, HID, D_OUT, 0,   out);
}